// round 4
// baseline (speedup 1.0000x reference)
#include <cuda_runtime.h>
#include <cuda_bf16.h>
#include <cstddef>
#include <cstdint>

#define DIMN   512
#define NSLOT  32
#define BATCH  32
#define TSTEPS 2048
#define RANKS  16     // d-chunks per cluster (cluster size)
#define BPC    4      // batches per CTA
#define DCH    32     // d columns per CTA
#define NTHR   256

// ---------------- scratch (static __device__ allocations only) ----------------
__device__ float g_pre[(size_t)BATCH * TSTEPS * DIMN];   // x@Wx^T + b_h
__device__ float g_WhP[DIMN * DIMN];                     // packed W_h  [k/4][d][4]
__device__ float g_WwP[DIMN * DIMN];                     // packed W_write

// ---------------- PTX helpers ----------------
__device__ __forceinline__ uint32_t smem_u32(const void* p) {
    uint32_t a;
    asm("{ .reg .u64 t; cvta.to.shared.u64 t, %1; cvt.u32.u64 %0, t; }"
        : "=r"(a) : "l"(p));
    return a;
}
__device__ __forceinline__ uint32_t mapa_rank(uint32_t laddr, uint32_t rank) {
    uint32_t r;
    asm("mapa.shared::cluster.u32 %0, %1, %2;" : "=r"(r) : "r"(laddr), "r"(rank));
    return r;
}
__device__ __forceinline__ void sts_cluster_f32(uint32_t addr, float v) {
    asm volatile("st.shared::cluster.f32 [%0], %1;" :: "r"(addr), "f"(v) : "memory");
}
__device__ __forceinline__ void sts_cluster_f32x2(uint32_t addr, float a, float b) {
    asm volatile("st.shared::cluster.v2.f32 [%0], {%1, %2};"
                 :: "r"(addr), "f"(a), "f"(b) : "memory");
}
__device__ __forceinline__ void mbar_init(uint32_t addr, uint32_t cnt) {
    asm volatile("mbarrier.init.shared.b64 [%0], %1;" :: "r"(addr), "r"(cnt) : "memory");
}
__device__ __forceinline__ void mbar_arrive_cl(uint32_t remAddr) {
    asm volatile("mbarrier.arrive.release.cluster.shared::cluster.b64 _, [%0];"
                 :: "r"(remAddr) : "memory");
}
__device__ __forceinline__ void mbar_wait_parity_cl(uint32_t addr, uint32_t parity) {
    asm volatile(
        "{\n\t"
        ".reg .pred P;\n\t"
        "LAB_WAIT_%=:\n\t"
        "mbarrier.try_wait.parity.acquire.cluster.shared::cta.b64 P, [%0], %1, 0x989680;\n\t"
        "@P bra.uni LAB_DONE_%=;\n\t"
        "bra.uni LAB_WAIT_%=;\n\t"
        "LAB_DONE_%=:\n\t"
        "}"
        :: "r"(addr), "r"(parity) : "memory");
}
__device__ __forceinline__ void cluster_sync_() {
    asm volatile("barrier.cluster.arrive.aligned;\n\tbarrier.cluster.wait.aligned;" ::: "memory");
}

// ---------------- weight packing ----------------
__global__ void pack_weights(const float* __restrict__ Wh,
                             const float* __restrict__ Ww) {
    int idx = blockIdx.x * blockDim.x + threadIdx.x;
    if (idx >= DIMN * DIMN) return;
    int d = idx / DIMN;
    int k = idx % DIMN;
    int dst = ((k >> 2) * DIMN + d) * 4 + (k & 3);
    g_WhP[dst] = Wh[idx];
    g_WwP[dst] = Ww[idx];
}

// ---------------- pre-GEMM (unchanged) ----------------
__global__ __launch_bounds__(256) void gemm_pre(
    const float* __restrict__ X,
    const float* __restrict__ W,
    const float* __restrict__ bias)
{
    __shared__ float As[8][128];
    __shared__ float Bs[8][64];

    const int tid = threadIdx.x;
    const int m0 = blockIdx.y * 128;
    const int n0 = blockIdx.x * 64;
    const int trow = tid >> 4;
    const int tcol = tid & 15;

    float acc[8][4];
#pragma unroll
    for (int i = 0; i < 8; ++i)
#pragma unroll
        for (int j = 0; j < 4; ++j) acc[i][j] = 0.f;

    const int a_m  = tid >> 1;
    const int a_k4 = (tid & 1) * 4;

    for (int k0 = 0; k0 < DIMN; k0 += 8) {
        float4 av = *reinterpret_cast<const float4*>(
            X + (size_t)(m0 + a_m) * DIMN + k0 + a_k4);
        As[a_k4 + 0][a_m] = av.x;
        As[a_k4 + 1][a_m] = av.y;
        As[a_k4 + 2][a_m] = av.z;
        As[a_k4 + 3][a_m] = av.w;
        if (tid < 128) {
            int bn  = tid >> 1;
            int bk4 = (tid & 1) * 4;
            float4 bv = *reinterpret_cast<const float4*>(
                W + (size_t)(n0 + bn) * DIMN + k0 + bk4);
            Bs[bk4 + 0][bn] = bv.x;
            Bs[bk4 + 1][bn] = bv.y;
            Bs[bk4 + 2][bn] = bv.z;
            Bs[bk4 + 3][bn] = bv.w;
        }
        __syncthreads();
#pragma unroll
        for (int kk = 0; kk < 8; ++kk) {
            float4 ra0 = *reinterpret_cast<const float4*>(&As[kk][trow * 8]);
            float4 ra1 = *reinterpret_cast<const float4*>(&As[kk][trow * 8 + 4]);
            float4 rb  = *reinterpret_cast<const float4*>(&Bs[kk][tcol * 4]);
            float ra[8] = {ra0.x, ra0.y, ra0.z, ra0.w, ra1.x, ra1.y, ra1.z, ra1.w};
            float rbv[4] = {rb.x, rb.y, rb.z, rb.w};
#pragma unroll
            for (int i = 0; i < 8; ++i)
#pragma unroll
                for (int j = 0; j < 4; ++j) acc[i][j] += ra[i] * rbv[j];
        }
        __syncthreads();
    }

    float4 bj = *reinterpret_cast<const float4*>(bias + n0 + tcol * 4);
#pragma unroll
    for (int i = 0; i < 8; ++i) {
        float4 v;
        v.x = acc[i][0] + bj.x;
        v.y = acc[i][1] + bj.y;
        v.z = acc[i][2] + bj.z;
        v.w = acc[i][3] + bj.w;
        *reinterpret_cast<float4*>(
            &g_pre[(size_t)(m0 + trow * 8 + i) * DIMN + n0 + tcol * 4]) = v;
    }
}

// ---------------- exact entmax-1.5 coefficient (warp-collective, lane=slot) ----
__device__ __forceinline__ float entmax_coef(float raw, float* __restrict__ sb, int lane) {
    const unsigned FULL = 0xffffffffu;
    float z = raw * 0.5f;
    float m = z;
#pragma unroll
    for (int o = 16; o > 0; o >>= 1) m = fmaxf(m, __shfl_xor_sync(FULL, m, o));
    z -= m;

    int rank = 0;
#pragma unroll
    for (int j = 0; j < 32; ++j) {
        float zj = __shfl_sync(FULL, z, j);
        rank += (zj > z) || (zj == z && j < lane);
    }
    sb[rank] = z;
    __syncwarp();
    float zs = sb[lane];

    float cs = zs, cq = zs * zs;
#pragma unroll
    for (int o = 1; o < 32; o <<= 1) {
        float a  = __shfl_up_sync(FULL, cs, o);
        float bq = __shfl_up_sync(FULL, cq, o);
        if (lane >= o) { cs += a; cq += bq; }
    }
    float k    = (float)(lane + 1);
    float mean = cs / k;
    float msq  = cq / k;
    float ss   = k * (msq - mean * mean);
    float delta = fmaxf((1.f - ss) / k, 0.f);
    float tau   = mean - sqrtf(delta);

    unsigned sup = __ballot_sync(FULL, tau <= zs);
    int kstar = __popc(sup) - 1;
    float tau_star = __shfl_sync(FULL, tau, kstar);
    float p = fmaxf(z - tau_star, 0.f);
    return p * p;
}

// ---------------- GEMV partials: warp=k-segment(64k), lane=d, 4 batches ----------
__device__ __forceinline__ void gemv8(const float* __restrict__ Wp,
                                      const float4* __restrict__ xw4,  // [4][128] float4
                                      float* __restrict__ part,
                                      int wid, int lane, int dglob) {
    const float4* W4 = reinterpret_cast<const float4*>(Wp)
                       + (size_t)(wid * 16) * DIMN + dglob;
    float a0 = 0.f, a1 = 0.f, a2 = 0.f, a3 = 0.f;
#pragma unroll
    for (int i = 0; i < 16; ++i) {
        float4 wm = W4[(size_t)i * DIMN];
        float4 k0 = xw4[0 * 128 + wid * 16 + i];
        float4 k1 = xw4[1 * 128 + wid * 16 + i];
        float4 k2 = xw4[2 * 128 + wid * 16 + i];
        float4 k3 = xw4[3 * 128 + wid * 16 + i];
        a0 += wm.x * k0.x + wm.y * k0.y + wm.z * k0.z + wm.w * k0.w;
        a1 += wm.x * k1.x + wm.y * k1.y + wm.z * k1.z + wm.w * k1.w;
        a2 += wm.x * k2.x + wm.y * k2.y + wm.z * k2.z + wm.w * k2.w;
        a3 += wm.x * k3.x + wm.y * k3.y + wm.z * k3.z + wm.w * k3.w;
    }
    part[wid * 128 +   0 + lane] = a0;
    part[wid * 128 +  32 + lane] = a1;
    part[wid * 128 +  64 + lane] = a2;
    part[wid * 128 +  96 + lane] = a3;
}

// ---------------- SMEM float offsets ----------------
#define SM_PART  0        // [8][4][32]            1024
#define SM_XW    1024     // [2][4][512]           4096
#define SM_WVEC  5120     // [4][32]               128
#define SM_COEFA 5248     // [4][32] alpha         128
#define SM_COEFB 5376     // [4][32] beta          128
#define SM_SORT  5504     // [4][32]               128
#define SM_TAPE  5632     // [4][32][33]           4224
#define SM_XC    9856     // [2][16][4][66]        8448
#define SM_MBARB 18304    // u64
#define SM_MBARC 18306    // u64
#define SM_FLOATS 18308

// ---------------- persistent recurrence ----------------
__global__ void __launch_bounds__(NTHR, 1) __cluster_dims__(RANKS, 1, 1)
recur3(const float* __restrict__ tape0,
       const float* __restrict__ work0,
       float* __restrict__ out_hseq,
       float* __restrict__ out_tape,
       float* __restrict__ out_hlast)
{
    extern __shared__ float sm[];
    float* part  = sm + SM_PART;
    float* xw    = sm + SM_XW;
    float* wvec  = sm + SM_WVEC;
    float* coefA = sm + SM_COEFA;
    float* coefB = sm + SM_COEFB;
    float* sortb = sm + SM_SORT;
    float* tape  = sm + SM_TAPE;
    float* xc    = sm + SM_XC;

    const int tid  = threadIdx.x;
    const int lane = tid & 31;
    const int wid  = tid >> 5;
    const int rk   = blockIdx.x & (RANKS - 1);   // cluster rank = d-chunk
    const int bg   = blockIdx.x / RANKS;         // batch group
    const int b0   = bg * BPC;
    const int dbase = rk * DCH;
    const int dglob = dbase + lane;

    const uint32_t sbase  = smem_u32(sm);
    const uint32_t a_xw   = sbase + SM_XW * 4u;
    const uint32_t a_xc   = sbase + SM_XC * 4u;
    const uint32_t a_mbB  = sbase + SM_MBARB * 4u;
    const uint32_t a_mbC  = sbase + SM_MBARC * 4u;

    if (tid == 0) {
        mbar_init(a_mbB, RANKS);
        mbar_init(a_mbC, RANKS);
    }

    // ---- prologue loads ----
    for (int i = tid; i < BPC * NSLOT * DCH; i += NTHR) {
        int b = i >> 10;
        int r = i & 1023;
        int n = r >> 5;
        int d = r & 31;
        tape[(b * NSLOT + n) * 33 + d] =
            tape0[((size_t)(b0 + b) * NSLOT + n) * DIMN + dbase + d];
    }
    for (int i = tid; i < BPC * DIMN; i += NTHR) {
        int b = i >> 9;
        int k = i & 511;
        xw[0 * 2048 + b * DIMN + k] = work0[(size_t)(b0 + b) * DIMN + k];
    }
    __syncthreads();
    cluster_sync_();   // mbarrier + smem visible cluster-wide

    const float invsd = 0.044194173824159216f;  // 1/sqrt(512)

    // ---- pre-loop: r_scores(0) partials -> exchange C (crossing 0, parity 0)
    if (wid < BPC) {
        const int b = wid;
        float s = 0.f;
        const float* tr = tape + (b * NSLOT + lane) * 33;
        const float* wk = xw + b * DIMN + dbase;
#pragma unroll
        for (int d = 0; d < DCH; ++d) s += tr[d] * wk[d];
        uint32_t off = a_xc + (unsigned)(0 * 4224 + rk * 264 + b * 66 + 2 * lane) * 4u;
#pragma unroll
        for (int p = 0; p < RANKS; ++p) sts_cluster_f32(mapa_rank(off, p), s);
    }
    __syncthreads();
    if (tid == 0) {
#pragma unroll
        for (int p = 0; p < RANKS; ++p) mbar_arrive_cl(mapa_rank(a_mbC, p));
    }
    mbar_wait_parity_cl(a_mbC, 0u);
    if (wid < BPC) {
        const int b = wid;
        float s = 0.f;
#pragma unroll
        for (int r = 0; r < RANKS; ++r) s += xc[r * 264 + b * 66 + 2 * lane];
        coefA[b * 32 + lane] = entmax_coef(s * invsd, sortb + b * 32, lane);
    }
    __syncthreads();

    float* hseq = out_hseq;

    for (int t = 0; t < TSTEPS; ++t) {
        const int oldi = t & 1;
        const int newi = oldi ^ 1;
        const int csl  = (t + 1) & 1;           // xc slot / C parity

        // prefetch pre (threads 0..127 = warps 0..3)
        float pre_v = 0.f;
        if (wid < BPC) {
            pre_v = __ldcs(&g_pre[((size_t)(b0 + wid) * TSTEPS + t) * DIMN + dglob]);
        }

        // ---- phase A: W_h GEMV partials ----
        gemv8(g_WhP, reinterpret_cast<const float4*>(xw + oldi * 2048), part,
              wid, lane, dglob);
        __syncthreads();

        // finish h chunk: threads 0..127, (b=wid, d=lane)
        if (wid < BPC) {
            const int b = wid, d = lane;
            float acc = pre_v;
#pragma unroll
            for (int w = 0; w < 8; ++w) acc += part[w * 128 + b * 32 + d];
            const float* tr = tape + b * NSLOT * 33 + d;
            const float* cf = coefA + b * 32;
#pragma unroll 8
            for (int n = 0; n < NSLOT; ++n) acc += cf[n] * tr[n * 33];
            float h = tanhf(acc);
            __stcs(&hseq[((size_t)(b0 + b) * TSTEPS + t) * DIMN + dglob], h);
            // push h to every rank's xw[newi]
            uint32_t off = a_xw + (unsigned)(newi * 2048 + b * DIMN + dglob) * 4u;
#pragma unroll
            for (int p = 0; p < RANKS; ++p) sts_cluster_f32(mapa_rank(off, p), h);
        }
        __syncthreads();
        if (tid == 0) {
#pragma unroll
            for (int p = 0; p < RANKS; ++p) mbar_arrive_cl(mapa_rank(a_mbB, p));
        }
        mbar_wait_parity_cl(a_mbB, (uint32_t)(t & 1));

        // ---- phase B: W_write GEMV partials on full h ----
        gemv8(g_WwP, reinterpret_cast<const float4*>(xw + newi * 2048), part,
              wid, lane, dglob);
        __syncthreads();
        if (wid < BPC) {
            const int b = wid, d = lane;
            float acc = 0.f;
#pragma unroll
            for (int w = 0; w < 8; ++w) acc += part[w * 128 + b * 32 + d];
            wvec[b * 32 + d] = acc;
        }
        __syncthreads();

        // ---- phase C: score partials sA=tape.wvec, sB=tape.h, sC=wvec.h ; push ----
        if (wid < BPC) {
            const int b = wid;
            float sA = 0.f, sB = 0.f;
            const float* tr = tape + (b * NSLOT + lane) * 33;
            const float* wv = wvec + b * 32;
            const float* hh = xw + newi * 2048 + b * DIMN + dbase;
#pragma unroll
            for (int d = 0; d < DCH; ++d) {
                float tv = tr[d];
                sA += tv * wv[d];
                sB += tv * hh[d];
            }
            uint32_t off = a_xc + (unsigned)(csl * 4224 + rk * 264 + b * 66 + 2 * lane) * 4u;
#pragma unroll
            for (int p = 0; p < RANKS; ++p) sts_cluster_f32x2(mapa_rank(off, p), sA, sB);
        } else {
            const int b = wid - BPC;
            float v = wvec[b * 32 + lane] * xw[newi * 2048 + b * DIMN + dbase + lane];
#pragma unroll
            for (int o = 16; o > 0; o >>= 1) v += __shfl_xor_sync(0xffffffffu, v, o);
            if (lane == 0) {
                uint32_t off = a_xc + (unsigned)(csl * 4224 + rk * 264 + b * 66 + 64) * 4u;
#pragma unroll
                for (int p = 0; p < RANKS; ++p) sts_cluster_f32(mapa_rank(off, p), v);
            }
        }
        __syncthreads();
        if (tid == 0) {
#pragma unroll
            for (int p = 0; p < RANKS; ++p) mbar_arrive_cl(mapa_rank(a_mbC, p));
        }
        mbar_wait_parity_cl(a_mbC, (uint32_t)csl);

        // ---- phase D: reduce; beta = entmax(w_scores); alpha_next via recurrence ----
        if (wid < BPC) {
            const int b = wid;
            float sA = 0.f, sB = 0.f, sC = 0.f;
            const float2* base2 = reinterpret_cast<const float2*>(
                xc + csl * 4224 + b * 66 + 2 * lane);
            const float*  baseC = xc + csl * 4224 + b * 66 + 64;
#pragma unroll
            for (int r = 0; r < RANKS; ++r) {
                float2 ab = base2[r * 132];           // 264 floats = 132 float2
                sA += ab.x;
                sB += ab.y;
                sC += baseC[r * 264];
            }
            float beta = entmax_coef(sA * invsd, sortb + b * 32, lane);
            coefB[b * 32 + lane] = beta;
            float rnext = ((1.f - beta) * sB + beta * sC) * invsd;
            coefA[b * 32 + lane] = entmax_coef(rnext, sortb + b * 32, lane);
        }
        __syncthreads();

        // ---- phase E: tape convex update (all 8 warps; n split in halves) ----
        {
            const int b = wid & 3;
            const int nh = (wid >> 2) * 16;
            const int d = lane;
            float wv = wvec[b * 32 + d];
            float* tr = tape + (b * NSLOT + nh) * 33 + d;
            const float* cf = coefB + b * 32 + nh;
#pragma unroll 8
            for (int n = 0; n < 16; ++n) {
                float bt = cf[n];
                tr[n * 33] = tr[n * 33] * (1.f - bt) + bt * wv;
            }
        }
        __syncthreads();
    }

    // ---- final outputs ----
    for (int i = tid; i < BPC * NSLOT * DCH; i += NTHR) {
        int b = i >> 10;
        int r = i & 1023;
        int n = r >> 5;
        int d = r & 31;
        out_tape[((size_t)(b0 + b) * NSLOT + n) * DIMN + dbase + d] =
            tape[(b * NSLOT + n) * 33 + d];
    }
    // h(T-1) lives in xw[ newi of t=2047 ] = xw[0]; each rank writes its k-slice
    if (wid < BPC) {
        out_hlast[(size_t)(b0 + wid) * DIMN + dglob] =
            xw[0 * 2048 + wid * DIMN + dglob];
    }
    cluster_sync_();
}

// ---------------- launch ----------------
extern "C" void kernel_launch(void* const* d_in, const int* in_sizes, int n_in,
                              void* d_out, int out_size) {
    const float* x     = (const float*)d_in[0];  // [B,T,D]
    const float* tape0 = (const float*)d_in[1];  // [B,N,D]
    const float* work0 = (const float*)d_in[2];  // [B,D]
    const float* Wh    = (const float*)d_in[3];  // [D,D]
    const float* Wx    = (const float*)d_in[4];  // [D,D]
    const float* bh    = (const float*)d_in[5];  // [D]
    const float* Ww    = (const float*)d_in[6];  // [D,D]

    float* out       = (float*)d_out;
    float* out_hseq  = out;
    float* out_tape  = out + (size_t)BATCH * TSTEPS * DIMN;
    float* out_hlast = out_tape + (size_t)BATCH * NSLOT * DIMN;

    pack_weights<<<(DIMN * DIMN + 511) / 512, 512>>>(Wh, Ww);

    dim3 ggrid(DIMN / 64, (BATCH * TSTEPS) / 128);
    gemm_pre<<<ggrid, 256>>>(x, Wx, bh);

    const int smem_bytes = SM_FLOATS * 4 + 16;
    cudaFuncSetAttribute(recur3, cudaFuncAttributeMaxDynamicSharedMemorySize, smem_bytes);
    cudaFuncSetAttribute(recur3, cudaFuncAttributeNonPortableClusterSizeAllowed, 1);
    recur3<<<(BATCH / BPC) * RANKS, NTHR, smem_bytes>>>(
        tape0, work0, out_hseq, out_tape, out_hlast);
}

// round 5
// speedup vs baseline: 2.2809x; 2.2809x over previous
#include <cuda_runtime.h>
#include <cuda_bf16.h>
#include <cstddef>
#include <cstdint>

#define DIMN   512
#define NSLOT  32
#define BATCH  32
#define TSTEPS 2048
#define RANKS  8      // cluster size = d-chunks
#define BPC    4      // batches per CTA
#define DCH    64     // d columns per CTA
#define NTHR   512

// ---------------- scratch ----------------
__device__ float g_pre[(size_t)BATCH * TSTEPS * DIMN];
__device__ float g_WhP[DIMN * DIMN];   // packed: float4 idx = k4*DIMN + d
__device__ float g_WwP[DIMN * DIMN];

// ---------------- PTX helpers ----------------
__device__ __forceinline__ uint32_t smem_u32(const void* p) {
    uint32_t a;
    asm("{ .reg .u64 t; cvta.to.shared.u64 t, %1; cvt.u32.u64 %0, t; }"
        : "=r"(a) : "l"(p));
    return a;
}
__device__ __forceinline__ uint32_t mapa_rank(uint32_t laddr, uint32_t rank) {
    uint32_t r;
    asm("mapa.shared::cluster.u32 %0, %1, %2;" : "=r"(r) : "r"(laddr), "r"(rank));
    return r;
}
__device__ __forceinline__ void sts_cluster_f32(uint32_t addr, float v) {
    asm volatile("st.shared::cluster.f32 [%0], %1;" :: "r"(addr), "f"(v) : "memory");
}
__device__ __forceinline__ void sts_cluster_f32x2(uint32_t addr, float a, float b) {
    asm volatile("st.shared::cluster.v2.f32 [%0], {%1, %2};"
                 :: "r"(addr), "f"(a), "f"(b) : "memory");
}
__device__ __forceinline__ void mbar_init(uint32_t addr, uint32_t cnt) {
    asm volatile("mbarrier.init.shared.b64 [%0], %1;" :: "r"(addr), "r"(cnt) : "memory");
}
__device__ __forceinline__ void mbar_arrive_cl(uint32_t remAddr) {
    asm volatile("mbarrier.arrive.release.cluster.shared::cluster.b64 _, [%0];"
                 :: "r"(remAddr) : "memory");
}
__device__ __forceinline__ void mbar_wait_parity_cl(uint32_t addr, uint32_t parity) {
    asm volatile(
        "{\n\t"
        ".reg .pred P;\n\t"
        "LAB_WAIT_%=:\n\t"
        "mbarrier.try_wait.parity.acquire.cluster.shared::cta.b64 P, [%0], %1, 0x989680;\n\t"
        "@P bra.uni LAB_DONE_%=;\n\t"
        "bra.uni LAB_WAIT_%=;\n\t"
        "LAB_DONE_%=:\n\t"
        "}"
        :: "r"(addr), "r"(parity) : "memory");
}
__device__ __forceinline__ void cluster_sync_() {
    asm volatile("barrier.cluster.arrive.aligned;\n\tbarrier.cluster.wait.aligned;" ::: "memory");
}

// ---------------- weight packing ----------------
__global__ void pack_weights(const float* __restrict__ Wh,
                             const float* __restrict__ Ww) {
    int idx = blockIdx.x * blockDim.x + threadIdx.x;
    if (idx >= DIMN * DIMN) return;
    int d = idx / DIMN;
    int k = idx % DIMN;
    int dst = ((k >> 2) * DIMN + d) * 4 + (k & 3);
    g_WhP[dst] = Wh[idx];
    g_WwP[dst] = Ww[idx];
}

// ---------------- pre-GEMM ----------------
__global__ __launch_bounds__(256) void gemm_pre(
    const float* __restrict__ X,
    const float* __restrict__ W,
    const float* __restrict__ bias)
{
    __shared__ float As[8][128];
    __shared__ float Bs[8][64];

    const int tid = threadIdx.x;
    const int m0 = blockIdx.y * 128;
    const int n0 = blockIdx.x * 64;
    const int trow = tid >> 4;
    const int tcol = tid & 15;

    float acc[8][4];
#pragma unroll
    for (int i = 0; i < 8; ++i)
#pragma unroll
        for (int j = 0; j < 4; ++j) acc[i][j] = 0.f;

    const int a_m  = tid >> 1;
    const int a_k4 = (tid & 1) * 4;

    for (int k0 = 0; k0 < DIMN; k0 += 8) {
        float4 av = *reinterpret_cast<const float4*>(
            X + (size_t)(m0 + a_m) * DIMN + k0 + a_k4);
        As[a_k4 + 0][a_m] = av.x;
        As[a_k4 + 1][a_m] = av.y;
        As[a_k4 + 2][a_m] = av.z;
        As[a_k4 + 3][a_m] = av.w;
        if (tid < 128) {
            int bn  = tid >> 1;
            int bk4 = (tid & 1) * 4;
            float4 bv = *reinterpret_cast<const float4*>(
                W + (size_t)(n0 + bn) * DIMN + k0 + bk4);
            Bs[bk4 + 0][bn] = bv.x;
            Bs[bk4 + 1][bn] = bv.y;
            Bs[bk4 + 2][bn] = bv.z;
            Bs[bk4 + 3][bn] = bv.w;
        }
        __syncthreads();
#pragma unroll
        for (int kk = 0; kk < 8; ++kk) {
            float4 ra0 = *reinterpret_cast<const float4*>(&As[kk][trow * 8]);
            float4 ra1 = *reinterpret_cast<const float4*>(&As[kk][trow * 8 + 4]);
            float4 rb  = *reinterpret_cast<const float4*>(&Bs[kk][tcol * 4]);
            float ra[8] = {ra0.x, ra0.y, ra0.z, ra0.w, ra1.x, ra1.y, ra1.z, ra1.w};
            float rbv[4] = {rb.x, rb.y, rb.z, rb.w};
#pragma unroll
            for (int i = 0; i < 8; ++i)
#pragma unroll
                for (int j = 0; j < 4; ++j) acc[i][j] += ra[i] * rbv[j];
        }
        __syncthreads();
    }

    float4 bj = *reinterpret_cast<const float4*>(bias + n0 + tcol * 4);
#pragma unroll
    for (int i = 0; i < 8; ++i) {
        float4 v;
        v.x = acc[i][0] + bj.x;
        v.y = acc[i][1] + bj.y;
        v.z = acc[i][2] + bj.z;
        v.w = acc[i][3] + bj.w;
        *reinterpret_cast<float4*>(
            &g_pre[(size_t)(m0 + trow * 8 + i) * DIMN + n0 + tcol * 4]) = v;
    }
}

// ---------------- exact entmax-1.5 (warp-collective, lane = slot) ----------------
__device__ __forceinline__ float entmax_coef(float raw, float* __restrict__ sb, int lane) {
    const unsigned FULL = 0xffffffffu;
    float z = raw * 0.5f;
    float m = z;
#pragma unroll
    for (int o = 16; o > 0; o >>= 1) m = fmaxf(m, __shfl_xor_sync(FULL, m, o));
    z -= m;

    int rank = 0;
#pragma unroll
    for (int j = 0; j < 32; ++j) {
        float zj = __shfl_sync(FULL, z, j);
        rank += (zj > z) || (zj == z && j < lane);
    }
    sb[rank] = z;
    __syncwarp();
    float zs = sb[lane];

    float cs = zs, cq = zs * zs;
#pragma unroll
    for (int o = 1; o < 32; o <<= 1) {
        float a  = __shfl_up_sync(FULL, cs, o);
        float bq = __shfl_up_sync(FULL, cq, o);
        if (lane >= o) { cs += a; cq += bq; }
    }
    float k    = (float)(lane + 1);
    float mean = cs / k;
    float msq  = cq / k;
    float ss   = k * (msq - mean * mean);
    float delta = fmaxf((1.f - ss) / k, 0.f);
    float tau   = mean - sqrtf(delta);

    unsigned sup = __ballot_sync(FULL, tau <= zs);
    int kstar = __popc(sup) - 1;
    float tau_star = __shfl_sync(FULL, tau, kstar);
    float p = fmaxf(z - tau_star, 0.f);
    return p * p;
}

// ---------------- GEMV partials: 16 warps = 16 k-segments of 32 ----------------
// part[seg][b][d] ; each lane covers d = lane and lane+32 ; 4 batches
__device__ __forceinline__ void gemv16(const float* __restrict__ Wp,
                                       const float4* __restrict__ xw4, // [4][128]
                                       float* __restrict__ part,
                                       int wid, int lane, int dbase) {
    const float4* W4 = reinterpret_cast<const float4*>(Wp)
                       + (size_t)(wid * 8) * DIMN + dbase + lane;
    float a0 = 0.f, a1 = 0.f, a2 = 0.f, a3 = 0.f;
    float b0 = 0.f, b1 = 0.f, b2 = 0.f, b3 = 0.f;
#pragma unroll
    for (int i = 0; i < 8; ++i) {
        float4 w0 = W4[(size_t)i * DIMN];
        float4 w1 = W4[(size_t)i * DIMN + 32];
        float4 k0 = xw4[0 * 128 + wid * 8 + i];
        float4 k1 = xw4[1 * 128 + wid * 8 + i];
        float4 k2 = xw4[2 * 128 + wid * 8 + i];
        float4 k3 = xw4[3 * 128 + wid * 8 + i];
        a0 += w0.x * k0.x + w0.y * k0.y + w0.z * k0.z + w0.w * k0.w;
        a1 += w0.x * k1.x + w0.y * k1.y + w0.z * k1.z + w0.w * k1.w;
        a2 += w0.x * k2.x + w0.y * k2.y + w0.z * k2.z + w0.w * k2.w;
        a3 += w0.x * k3.x + w0.y * k3.y + w0.z * k3.z + w0.w * k3.w;
        b0 += w1.x * k0.x + w1.y * k0.y + w1.z * k0.z + w1.w * k0.w;
        b1 += w1.x * k1.x + w1.y * k1.y + w1.z * k1.z + w1.w * k1.w;
        b2 += w1.x * k2.x + w1.y * k2.y + w1.z * k2.z + w1.w * k2.w;
        b3 += w1.x * k3.x + w1.y * k3.y + w1.z * k3.z + w1.w * k3.w;
    }
    float* pp = part + wid * 256 + lane;
    pp[0]        = a0;  pp[64]       = a1;  pp[128]      = a2;  pp[192]      = a3;
    pp[32]       = b0;  pp[96]       = b1;  pp[160]      = b2;  pp[224]      = b3;
}

// ---------------- SMEM float offsets ----------------
#define SM_PART   0       // [16][4][64]          4096
#define SM_XW     4096    // [2][4][512]          4096
#define SM_WVEC   8192    // [4][64]              256
#define SM_COEFA  8448    // [4][32]              128
#define SM_COEFB  8576    // [4][32]              128
#define SM_SORT   8704    // [4][32]              128
#define SM_TAPE   8832    // [4][32][65]          8320
#define SM_XC     17152   // [2][8][4][130]       8320
#define SM_MBARB  25472   // u64
#define SM_MBARC  25474   // u64
#define SM_FLOATS 25476

// ---------------- persistent recurrence ----------------
__global__ void __launch_bounds__(NTHR, 1) __cluster_dims__(RANKS, 1, 1)
recur5(const float* __restrict__ tape0,
       const float* __restrict__ work0,
       float* __restrict__ out_hseq,
       float* __restrict__ out_tape,
       float* __restrict__ out_hlast)
{
    extern __shared__ float sm[];
    float* part  = sm + SM_PART;
    float* xw    = sm + SM_XW;
    float* wvec  = sm + SM_WVEC;
    float* coefA = sm + SM_COEFA;
    float* coefB = sm + SM_COEFB;
    float* sortb = sm + SM_SORT;
    float* tape  = sm + SM_TAPE;
    float* xc    = sm + SM_XC;

    const int tid  = threadIdx.x;
    const int lane = tid & 31;
    const int wid  = tid >> 5;
    const int rk   = blockIdx.x & (RANKS - 1);
    const int bg   = blockIdx.x / RANKS;
    const int b0   = bg * BPC;
    const int dbase = rk * DCH;

    const uint32_t sbase = smem_u32(sm);
    const uint32_t a_xw  = sbase + SM_XW * 4u;
    const uint32_t a_xc  = sbase + SM_XC * 4u;
    const uint32_t a_mbB = sbase + SM_MBARB * 4u;
    const uint32_t a_mbC = sbase + SM_MBARC * 4u;

    if (tid == 0) {
        mbar_init(a_mbB, RANKS);
        mbar_init(a_mbC, RANKS);
    }

    // ---- prologue loads ----
    for (int i = tid; i < BPC * NSLOT * DCH; i += NTHR) {
        int b = i >> 11;
        int r = i & 2047;
        int n = r >> 6;
        int d = r & 63;
        tape[(b * NSLOT + n) * 65 + d] =
            tape0[((size_t)(b0 + b) * NSLOT + n) * DIMN + dbase + d];
    }
    for (int i = tid; i < BPC * DIMN; i += NTHR) {
        int b = i >> 9;
        int k = i & 511;
        xw[b * DIMN + k] = work0[(size_t)(b0 + b) * DIMN + k];
    }
    __syncthreads();
    cluster_sync_();

    const float invsd = 0.044194173824159216f;  // 1/sqrt(512)

    // ---- pre-loop: r_scores(0) partials -> exchange C, parity 0 ----
    if (wid < 8) {
        const int b = wid & 3, half = wid >> 2;
        const float* tr = tape + (b * NSLOT + lane) * 65 + half * 32;
        const float* wk = xw + b * DIMN + dbase + half * 32;
        float s = 0.f;
#pragma unroll
        for (int d = 0; d < 32; ++d) s += tr[d] * wk[d];
        uint32_t off = a_xc + (unsigned)(rk * 520 + b * 130 + 2 * (half * 32 + lane)) * 4u;
#pragma unroll
        for (int p = 0; p < RANKS; ++p) sts_cluster_f32(mapa_rank(off, p), s);
    }
    __syncthreads();
    if (tid == 0) {
#pragma unroll
        for (int p = 0; p < RANKS; ++p) mbar_arrive_cl(mapa_rank(a_mbC, p));
    }
    mbar_wait_parity_cl(a_mbC, 0u);
    if (wid < BPC) {
        const int b = wid;
        const float* base = xc + b * 130 + 2 * lane;
        float s = 0.f;
#pragma unroll
        for (int r = 0; r < RANKS; ++r) s += base[r * 520] + base[r * 520 + 64];
        coefA[b * 32 + lane] = entmax_coef(s * invsd, sortb + b * 32, lane);
    }
    __syncthreads();

    for (int t = 0; t < TSTEPS; ++t) {
        const int oldi = t & 1;
        const int newi = oldi ^ 1;
        const int csl  = (t + 1) & 1;

        // prefetch pre (tid<256: b=tid>>6, d=tid&63)
        float pre_v = 0.f;
        if (tid < 256) {
            pre_v = __ldcs(&g_pre[((size_t)(b0 + (tid >> 6)) * TSTEPS + t) * DIMN
                                  + dbase + (tid & 63)]);
        }

        // ---- phase A: W_h GEMV partials (16 warps) ----
        gemv16(g_WhP, reinterpret_cast<const float4*>(xw + oldi * 2048), part,
               wid, lane, dbase);
        __syncthreads();

        // finish h chunk (tid<256): reduce 16 partials + alpha.tape + tanh; push h
        if (tid < 256) {
            const int b = tid >> 6, d = tid & 63;
            float acc = pre_v;
#pragma unroll
            for (int s = 0; s < 16; ++s) acc += part[s * 256 + b * 64 + d];
            const float* tr = tape + b * NSLOT * 65 + d;
            const float* cf = coefA + b * 32;
#pragma unroll 8
            for (int n = 0; n < NSLOT; ++n) acc += cf[n] * tr[n * 65];
            float h = tanhf(acc);
            __stcs(&out_hseq[((size_t)(b0 + b) * TSTEPS + t) * DIMN + dbase + d], h);
            uint32_t off = a_xw + (unsigned)(newi * 2048 + b * DIMN + dbase + d) * 4u;
#pragma unroll
            for (int p = 0; p < RANKS; ++p) sts_cluster_f32(mapa_rank(off, p), h);
        }
        __syncthreads();
        if (tid == 0) {
#pragma unroll
            for (int p = 0; p < RANKS; ++p) mbar_arrive_cl(mapa_rank(a_mbB, p));
        }
        mbar_wait_parity_cl(a_mbB, (uint32_t)(t & 1));

        // ---- phase B: W_write GEMV partials on full h ----
        gemv16(g_WwP, reinterpret_cast<const float4*>(xw + newi * 2048), part,
               wid, lane, dbase);
        __syncthreads();
        if (tid < 256) {
            const int b = tid >> 6, d = tid & 63;
            float acc = 0.f;
#pragma unroll
            for (int s = 0; s < 16; ++s) acc += part[s * 256 + b * 64 + d];
            wvec[b * 64 + d] = acc;
        }
        __syncthreads();

        // ---- phase C: score partials; warps 0-7: (sA,sB); warps 8-11: sC ----
        if (wid < 8) {
            const int b = wid & 3, half = wid >> 2;
            const float* tr = tape + (b * NSLOT + lane) * 65 + half * 32;
            const float* wv = wvec + b * 64 + half * 32;
            const float* hh = xw + newi * 2048 + b * DIMN + dbase + half * 32;
            float sA = 0.f, sB = 0.f;
#pragma unroll
            for (int d = 0; d < 32; ++d) {
                float tv = tr[d];
                sA += tv * wv[d];
                sB += tv * hh[d];
            }
            uint32_t off = a_xc + (unsigned)(csl * 4160 + rk * 520 + b * 130
                                             + 2 * (half * 32 + lane)) * 4u;
#pragma unroll
            for (int p = 0; p < RANKS; ++p) sts_cluster_f32x2(mapa_rank(off, p), sA, sB);
        } else if (wid < 12) {
            const int b = wid - 8;
            float v = wvec[b * 64 + lane] * xw[newi * 2048 + b * DIMN + dbase + lane]
                    + wvec[b * 64 + 32 + lane] * xw[newi * 2048 + b * DIMN + dbase + 32 + lane];
#pragma unroll
            for (int o = 16; o > 0; o >>= 1) v += __shfl_xor_sync(0xffffffffu, v, o);
            if (lane == 0) {
                uint32_t off = a_xc + (unsigned)(csl * 4160 + rk * 520 + b * 130 + 128) * 4u;
#pragma unroll
                for (int p = 0; p < RANKS; ++p) sts_cluster_f32(mapa_rank(off, p), v);
            }
        }
        __syncthreads();
        if (tid == 0) {
#pragma unroll
            for (int p = 0; p < RANKS; ++p) mbar_arrive_cl(mapa_rank(a_mbC, p));
        }
        mbar_wait_parity_cl(a_mbC, (uint32_t)csl);

        // ---- phase D: reduce; beta = entmax(sA); alpha_next via score recurrence ----
        if (wid < BPC) {
            const int b = wid;
            const float* base = xc + csl * 4160 + b * 130;
            float sA = 0.f, sB = 0.f, sC = 0.f;
#pragma unroll
            for (int r = 0; r < RANKS; ++r) {
                float2 p0 = *reinterpret_cast<const float2*>(base + r * 520 + 2 * lane);
                float2 p1 = *reinterpret_cast<const float2*>(base + r * 520 + 64 + 2 * lane);
                sA += p0.x + p1.x;
                sB += p0.y + p1.y;
                sC += base[r * 520 + 128];
            }
            float beta = entmax_coef(sA * invsd, sortb + b * 32, lane);
            coefB[b * 32 + lane] = beta;
            float rnext = ((1.f - beta) * sB + beta * sC) * invsd;
            coefA[b * 32 + lane] = entmax_coef(rnext, sortb + b * 32, lane);
        }
        __syncthreads();

        // ---- phase E: tape convex update (16 warps: b, 8-slot group) ----
        {
            const int b = wid & 3;
            const int n0 = (wid >> 2) * 8;
            const float* wv = wvec + b * 64;
            const float* cf = coefB + b * 32 + n0;
            float* tb = tape + (b * NSLOT + n0) * 65;
#pragma unroll
            for (int n = 0; n < 8; ++n) {
                float bt = cf[n];
                float* tr = tb + n * 65;
                tr[lane]      = tr[lane]      * (1.f - bt) + bt * wv[lane];
                tr[lane + 32] = tr[lane + 32] * (1.f - bt) + bt * wv[lane + 32];
            }
        }
        __syncthreads();
    }

    // ---- final outputs ----
    for (int i = tid; i < BPC * NSLOT * DCH; i += NTHR) {
        int b = i >> 11;
        int r = i & 2047;
        int n = r >> 6;
        int d = r & 63;
        out_tape[((size_t)(b0 + b) * NSLOT + n) * DIMN + dbase + d] =
            tape[(b * NSLOT + n) * 65 + d];
    }
    if (tid < 256) {
        const int b = tid >> 6, d = tid & 63;
        // h(T-1): t=2047 -> newi = 0
        out_hlast[(size_t)(b0 + b) * DIMN + dbase + d] = xw[b * DIMN + dbase + d];
    }
    cluster_sync_();
}

// ---------------- launch ----------------
extern "C" void kernel_launch(void* const* d_in, const int* in_sizes, int n_in,
                              void* d_out, int out_size) {
    const float* x     = (const float*)d_in[0];
    const float* tape0 = (const float*)d_in[1];
    const float* work0 = (const float*)d_in[2];
    const float* Wh    = (const float*)d_in[3];
    const float* Wx    = (const float*)d_in[4];
    const float* bh    = (const float*)d_in[5];
    const float* Ww    = (const float*)d_in[6];

    float* out       = (float*)d_out;
    float* out_hseq  = out;
    float* out_tape  = out + (size_t)BATCH * TSTEPS * DIMN;
    float* out_hlast = out_tape + (size_t)BATCH * NSLOT * DIMN;

    pack_weights<<<(DIMN * DIMN + 511) / 512, 512>>>(Wh, Ww);

    dim3 ggrid(DIMN / 64, (BATCH * TSTEPS) / 128);
    gemm_pre<<<ggrid, 256>>>(x, Wx, bh);

    const int smem_bytes = SM_FLOATS * 4 + 16;
    cudaFuncSetAttribute(recur5, cudaFuncAttributeMaxDynamicSharedMemorySize, smem_bytes);
    recur5<<<(BATCH / BPC) * RANKS, NTHR, smem_bytes>>>(
        tape0, work0, out_hseq, out_tape, out_hlast);
}